// round 1
// baseline (speedup 1.0000x reference)
#include <cuda_runtime.h>
#include <cstdint>
#include <cstddef>

// Problem constants (fixed by the reference)
#define HD 1024      // H
#define ID 2048      // I
#define NSTATE 16    // N
#define RD 64        // R
#define BB 2         // batch
#define LL 512       // seq len
#define ML (BB*LL)   // 1024 token rows

// ---------------------------------------------------------------------------
// Scratch (static device globals; no runtime allocation allowed)
// ---------------------------------------------------------------------------
__device__ float g_x   [(size_t)ML*ID];        // pre-conv x
__device__ float g_gate[(size_t)ML*ID];        // gate (pre-silu)
__device__ float g_u   [(size_t)ML*ID];        // post conv+silu
__device__ float g_ssm [2][(size_t)ML*96];     // [dir] (M,96): [0:64 dt_r | 64:80 B | 80:96 C]
__device__ float g_delta[2][(size_t)ML*ID];    // [dir] softplus delta
__device__ float g_y   [2][(size_t)ML*ID];     // [dir] raw scan output (incl. u*D)
__device__ float g_yt  [(size_t)ML*ID];        // (yf+yb)*silu(gate)

__device__ __forceinline__ float siluf(float v)     { return v * (1.0f / (1.0f + __expf(-v))); }
__device__ __forceinline__ float softplusf(float v) { return v > 20.f ? v : log1pf(__expf(v)); }

// ---------------------------------------------------------------------------
// Generic SGEMM: C[M,N] = A[M,K] @ B[N,K]^T   (both row-major, weight-style B)
// Dual-problem via blockIdx.z (two independent arg sets, same shape).
// EPI: 0 = plain store, 1 = softplus(acc + bias[col])
// ---------------------------------------------------------------------------
struct GemmArgs {
    const float* A;
    const float* B;
    float*       C;
    const float* bias;
};

template<int BM, int BN, int BK, int TM, int TN, int EPI>
__global__ __launch_bounds__((BM/TM)*(BN/TN))
void sgemm(GemmArgs g0, GemmArgs g1, int lda, int ldb, int ldc, int K)
{
    constexpr int THREADS = (BM/TM)*(BN/TN);
    constexpr int KV = BK/4;
    static_assert(BM % TM == 0 && BN % TN == 0 && BK % 4 == 0, "");
    static_assert(TM % 4 == 0 && (TN % 4 == 0 || TN == 2), "");

    __shared__ float As[BK][BM];
    __shared__ float Bs[BK][BN];

    GemmArgs g = (blockIdx.z == 0) ? g0 : g1;

    const int tid  = threadIdx.x;
    const int row0 = blockIdx.y * BM;
    const int col0 = blockIdx.x * BN;
    const float* __restrict__ Ap = g.A + (size_t)row0 * lda;
    const float* __restrict__ Bp = g.B + (size_t)col0 * ldb;

    float acc[TM][TN];
#pragma unroll
    for (int i = 0; i < TM; i++)
#pragma unroll
        for (int j = 0; j < TN; j++) acc[i][j] = 0.f;

    const int tcol = tid % (BN/TN);
    const int trow = tid / (BN/TN);

    for (int k0 = 0; k0 < K; k0 += BK) {
        // stage A tile (transposed into smem)
#pragma unroll
        for (int idx = tid; idx < BM*KV; idx += THREADS) {
            int r = idx / KV, kv = idx % KV;
            float4 v = *reinterpret_cast<const float4*>(Ap + (size_t)r*lda + k0 + kv*4);
            As[kv*4+0][r] = v.x; As[kv*4+1][r] = v.y;
            As[kv*4+2][r] = v.z; As[kv*4+3][r] = v.w;
        }
        // stage B tile
#pragma unroll
        for (int idx = tid; idx < BN*KV; idx += THREADS) {
            int r = idx / KV, kv = idx % KV;
            float4 v = *reinterpret_cast<const float4*>(Bp + (size_t)r*ldb + k0 + kv*4);
            Bs[kv*4+0][r] = v.x; Bs[kv*4+1][r] = v.y;
            Bs[kv*4+2][r] = v.z; Bs[kv*4+3][r] = v.w;
        }
        __syncthreads();

#pragma unroll
        for (int k = 0; k < BK; k++) {
            float a[TM], b[TN];
#pragma unroll
            for (int i = 0; i < TM; i += 4) {
                float4 v = *reinterpret_cast<const float4*>(&As[k][trow*TM + i]);
                a[i] = v.x; a[i+1] = v.y; a[i+2] = v.z; a[i+3] = v.w;
            }
            if constexpr (TN == 2) {
                float2 v = *reinterpret_cast<const float2*>(&Bs[k][tcol*TN]);
                b[0] = v.x; b[1] = v.y;
            } else {
#pragma unroll
                for (int j = 0; j < TN; j += 4) {
                    float4 v = *reinterpret_cast<const float4*>(&Bs[k][tcol*TN + j]);
                    b[j] = v.x; b[j+1] = v.y; b[j+2] = v.z; b[j+3] = v.w;
                }
            }
#pragma unroll
            for (int i = 0; i < TM; i++)
#pragma unroll
                for (int j = 0; j < TN; j++)
                    acc[i][j] = fmaf(a[i], b[j], acc[i][j]);
        }
        __syncthreads();
    }

#pragma unroll
    for (int i = 0; i < TM; i++) {
        int r = row0 + trow*TM + i;
#pragma unroll
        for (int j = 0; j < TN; j++) {
            int c = col0 + tcol*TN + j;
            float v = acc[i][j];
            if (EPI == 1) v = softplusf(v + g.bias[c]);
            g.C[(size_t)r*ldc + c] = v;
        }
    }
}

// ---------------------------------------------------------------------------
// Depthwise causal conv (K=4) + bias + silu : g_x -> g_u
// ---------------------------------------------------------------------------
__global__ void conv_silu_kernel(const float* __restrict__ w,
                                 const float* __restrict__ bias)
{
    int idx = blockIdx.x * blockDim.x + threadIdx.x;   // over ML*ID
    int i = idx % ID;
    int l = (idx / ID) % LL;
    float acc = bias[i];
#pragma unroll
    for (int k = 0; k < 4; k++) {
        int ls = l - 3 + k;
        if (ls >= 0) acc = fmaf(g_x[(size_t)idx + (ptrdiff_t)(k-3)*ID], w[i*4 + k], acc);
    }
    g_u[idx] = siluf(acc);
}

// ---------------------------------------------------------------------------
// Selective scan. One warp handles two channels (i0,i1); within each half-warp
// lane = state index n (16 states in flight). Sequential over L.
// dir=0: forward scan; dir=1: backward scan (iterates forward index L-1..0,
// which is exactly the reversed-sequence scan; output lands at forward index).
// ---------------------------------------------------------------------------
__global__ void scan_kernel(const float* __restrict__ Alog_f,
                            const float* __restrict__ Alog_b,
                            const float* __restrict__ D_f,
                            const float* __restrict__ D_b)
{
    int gw   = (blockIdx.x * blockDim.x + threadIdx.x) >> 5;  // global warp id, < 4096
    int lane = threadIdx.x & 31;
    int dir  = gw >> 11;
    int b    = (gw >> 10) & 1;
    int i    = ((gw & 1023) << 1) | (lane >> 4);
    int n    = lane & 15;

    const float* Alog = dir ? Alog_b : Alog_f;
    float An = -expf(Alog[i*NSTATE + n]);
    float Dv = dir ? D_b[i] : D_f[i];

    const float* dbase = g_delta[dir] + (size_t)(b*LL)*ID + i;
    const float* ubase = g_u          + (size_t)(b*LL)*ID + i;
    const float* sbase = g_ssm[dir]   + (size_t)(b*LL)*96;
    float*       ybase = g_y[dir]     + (size_t)(b*LL)*ID + i;

    int l0 = dir ? (LL-1) : 0;
    ptrdiff_t dstep = dir ? -(ptrdiff_t)ID : (ptrdiff_t)ID;
    ptrdiff_t sstep = dir ? -96 : 96;

    const float* dp = dbase + (size_t)l0*ID;
    const float* up = ubase + (size_t)l0*ID;
    const float* sp = sbase + (size_t)l0*96;
    float*       yp = ybase + (size_t)l0*ID;

    float x = 0.f;
    for (int t = 0; t < LL; t++) {
        float d  = __ldg(dp);
        float uu = __ldg(up);
        float Bv = __ldg(sp + RD + n);
        float Cv = __ldg(sp + RD + NSTATE + n);
        float dA = __expf(d * An);
        x = fmaf(x, dA, d * Bv * uu);
        float p = x * Cv;
        p += __shfl_xor_sync(0xffffffffu, p, 1);
        p += __shfl_xor_sync(0xffffffffu, p, 2);
        p += __shfl_xor_sync(0xffffffffu, p, 4);
        p += __shfl_xor_sync(0xffffffffu, p, 8);
        if (n == 0) *yp = fmaf(uu, Dv, p);
        dp += dstep; up += dstep; sp += sstep; yp += dstep;
    }
}

// ---------------------------------------------------------------------------
// yt = (yf + yb) * silu(gate)
// ---------------------------------------------------------------------------
__global__ void combine_kernel()
{
    int idx = blockIdx.x * blockDim.x + threadIdx.x;
    g_yt[idx] = (g_y[0][idx] + g_y[1][idx]) * siluf(g_gate[idx]);
}

// ---------------------------------------------------------------------------
// Launch
// ---------------------------------------------------------------------------
extern "C" void kernel_launch(void* const* d_in, const int* in_sizes, int n_in,
                              void* d_out, int out_size)
{
    const float* hs     = (const float*)d_in[0];   // (2,512,1024)
    const float* hs2    = (const float*)d_in[1];   // (2,512,1024)
    const float* in_w   = (const float*)d_in[2];   // (4096,1024)
    const float* in_dw  = (const float*)d_in[3];   // (4096,1024)
    const float* conv_w = (const float*)d_in[4];   // (2048,4)
    const float* conv_b = (const float*)d_in[5];   // (2048,)
    const float* xw_f   = (const float*)d_in[6];   // (96,2048)
    const float* xw_b   = (const float*)d_in[7];   // (96,2048)
    const float* dtw_f  = (const float*)d_in[8];   // (2048,64)
    const float* dtb_f  = (const float*)d_in[9];   // (2048,)
    const float* dtw_b  = (const float*)d_in[10];  // (2048,64)
    const float* dtb_b  = (const float*)d_in[11];  // (2048,)
    const float* Alog_f = (const float*)d_in[12];  // (2048,16)
    const float* Alog_b = (const float*)d_in[13];
    const float* D_f    = (const float*)d_in[14];  // (2048,)
    const float* D_b    = (const float*)d_in[15];
    const float* outw   = (const float*)d_in[16];  // (1024,2048)
    float* out = (float*)d_out;                    // (2,512,1024)

    float *px, *pgate, *pu, *pssm, *pdelta, *pyt;
    cudaGetSymbolAddress((void**)&px,     g_x);
    cudaGetSymbolAddress((void**)&pgate,  g_gate);
    cudaGetSymbolAddress((void**)&pu,     g_u);
    cudaGetSymbolAddress((void**)&pssm,   g_ssm);
    cudaGetSymbolAddress((void**)&pdelta, g_delta);
    cudaGetSymbolAddress((void**)&pyt,    g_yt);
    float* pssm0 = pssm;
    float* pssm1 = pssm + (size_t)ML*96;
    float* pd0   = pdelta;
    float* pd1   = pdelta + (size_t)ML*ID;

    // G1: x = hs @ in_proj_w[:I]^T ; G2: gate = hs2 @ in_proj_dif_w[I:2I]^T
    {
        GemmArgs a{hs,  in_w,                       px,    nullptr};
        GemmArgs b{hs2, in_dw + (size_t)ID * HD,    pgate, nullptr};
        dim3 grid(ID/64, ML/128, 2);
        sgemm<128,64,8,8,4,0><<<grid, 256>>>(a, b, HD, HD, ID, HD);
    }

    // conv + silu -> u
    conv_silu_kernel<<<(ML*ID)/256, 256>>>(conv_w, conv_b);

    // G3: ssm[dir] = u @ x_proj(_back)_w^T   (M=1024, N=96, K=2048)
    {
        GemmArgs a{pu, xw_f, pssm0, nullptr};
        GemmArgs b{pu, xw_b, pssm1, nullptr};
        dim3 grid(96/32, ML/64, 2);
        sgemm<64,32,16,4,2,0><<<grid, 256>>>(a, b, ID, ID, 96, ID);
    }

    // G4: delta[dir] = softplus(ssm[:, :64] @ dt_proj(_back)_w^T + bias)
    {
        GemmArgs a{pssm0, dtw_f, pd0, dtb_f};
        GemmArgs b{pssm1, dtw_b, pd1, dtb_b};
        dim3 grid(ID/64, ML/64, 2);
        sgemm<64,64,16,4,4,1><<<grid, 256>>>(a, b, 96, RD, ID, RD);
    }

    // scan (both directions)
    scan_kernel<<<512, 256>>>(Alog_f, Alog_b, D_f, D_b);

    // combine with gate
    combine_kernel<<<(ML*ID)/256, 256>>>();

    // G5: out = yt @ out_proj_w^T  (M=1024, N=1024, K=2048)
    {
        GemmArgs a{pyt, outw, out, nullptr};
        GemmArgs b{pyt, outw, out, nullptr};
        dim3 grid(HD/64, ML/128, 1);
        sgemm<128,64,8,8,4,0><<<grid, 256>>>(a, b, ID, ID, HD, ID);
    }

    (void)in_sizes; (void)n_in; (void)out_size;
}